// round 12
// baseline (speedup 1.0000x reference)
#include <cuda_runtime.h>
#include <math.h>

#define B1n 4
#define B2n 1024
#define Rn  64
#define Tn  8192
#define Ln  256

// 256 threads = 64 l-threads x 4 r-groups (16 receivers each).
// Receivers counting-sorted by d = i0 & 3 (deterministic, match-based); four
// d-specialized sub-loops, alignment resolved at compile time. Lerp + moment
// accumulation done with packed f32x2 (Blackwell): e = g*w + f*w' pairs,
// packed accumulators carried across the loop.

typedef unsigned long long u64;

__device__ __forceinline__ u64 pack2(float lo, float hi) {
    u64 r; asm("mov.b64 %0, {%1, %2};" : "=l"(r) : "f"(lo), "f"(hi)); return r;
}
__device__ __forceinline__ void unpack2(u64 v, float& lo, float& hi) {
    asm("mov.b64 {%0, %1}, %2;" : "=f"(lo), "=f"(hi) : "l"(v));
}
__device__ __forceinline__ u64 mul2(u64 a, u64 b) {
    u64 r; asm("mul.rn.f32x2 %0, %1, %2;" : "=l"(r) : "l"(a), "l"(b)); return r;
}
__device__ __forceinline__ u64 add2(u64 a, u64 b) {
    u64 r; asm("add.rn.f32x2 %0, %1, %2;" : "=l"(r) : "l"(a), "l"(b)); return r;
}
__device__ __forceinline__ u64 fma2(u64 a, u64 b, u64 c) {
    u64 r; asm("fma.rn.f32x2 %0, %1, %2, %3;" : "=l"(r) : "l"(a), "l"(b), "l"(c)); return r;
}

template<int D>
__device__ __forceinline__ void body_d(float2 pr, const float* recb, int lane,
                                       u64& A01, u64& A23, u64& Q01, u64& Q23)
{
    const unsigned FULL = 0xFFFFFFFFu;
    float f = pr.x;
    float g = 1.0f - f;
    int   o = __float_as_int(pr.y);
    const float4* p = (const float4*)(recb + o);

    float w0, w1, w2, w3, w4;
    if (D == 0) {
        float4 A = __ldg(p);
        float v4 = __shfl_down_sync(FULL, A.x, 1);
        if (lane == 31) v4 = __ldg((const float*)p + 4);
        w0 = A.x; w1 = A.y; w2 = A.z; w3 = A.w; w4 = v4;
    } else if (D == 1) {
        float4 A = __ldg(p);
        float4 B = __ldg(p + 1);
        w0 = A.y; w1 = A.z; w2 = A.w; w3 = B.x; w4 = B.y;
    } else if (D == 2) {
        float4 A = __ldg(p);
        float4 B = __ldg(p + 1);
        w0 = A.z; w1 = A.w; w2 = B.x; w3 = B.y; w4 = B.z;
    } else {
        float4 B = __ldg(p + 1);
        float vm = __shfl_up_sync(FULL, B.w, 1);
        if (lane == 0) vm = __ldg((const float*)p + 3);
        w0 = vm; w1 = B.x; w2 = B.y; w3 = B.z; w4 = B.w;
    }

    u64 F2  = pack2(f, f);
    u64 G2  = pack2(g, g);
    u64 W01 = pack2(w0, w1);
    u64 V12 = pack2(w1, w2);
    u64 W23 = pack2(w2, w3);
    u64 V34 = pack2(w3, w4);

    // e_j = g*w_j + f*w_{j+1}
    u64 E01 = fma2(F2, V12, mul2(G2, W01));
    u64 E23 = fma2(F2, V34, mul2(G2, W23));

    A01 = add2(A01, E01);
    A23 = add2(A23, E23);
    Q01 = fma2(E01, E01, Q01);
    Q23 = fma2(E23, E23, Q23);
}

__global__ void __launch_bounds__(Ln)
tof_predictor_kernel(const float* __restrict__ rec,        // (B1,R,T)
                     const float* __restrict__ samp,       // (B1,B2,3)
                     const float* __restrict__ emit,       // (3,)
                     const float* __restrict__ recv,       // (R,3)
                     float* __restrict__ out)              // (B1,B2)
{
    const int b2  = blockIdx.x;
    const int b1  = blockIdx.y;
    const int tid = threadIdx.x;

    __shared__ float2 s_sorted[Rn];      // per-group, d-sorted {frac, as_float(r*Tn+i0a)}
    __shared__ int    s_cnt[4][4];       // [group][d] counts (scratch)
    __shared__ int    s_start[4][4];     // [group][d] bucket start
    __shared__ int    s_bnd[4][4];       // [group][d] bucket end
    __shared__ float  s_s1[4 * Ln];
    __shared__ float  s_s2[4 * Ln];
    __shared__ float  s_red[16];

    // ---- precompute + deterministic counting sort by d (threads 0..63) ----
    const float fs_c = 96000.0f / 343.0f;
    if (tid < 16) s_cnt[tid >> 2][tid & 3] = 0;
    __syncthreads();

    float2 packed;
    int my_d = 0, my_rank = 0, my_g = 0;
    if (tid < Rn) {
        const float* sp = samp + ((size_t)b1 * B2n + b2) * 3;
        float sx = sp[0], sy = sp[1], sz = sp[2];
        float ex = sx - emit[0], ey = sy - emit[1], ez = sz - emit[2];
        float d_e = sqrtf(ex * ex + ey * ey + ez * ez);
        const float* rp = recv + tid * 3;
        float rx = sx - rp[0], ry = sy - rp[1], rz = sz - rp[2];
        float d_r = sqrtf(rx * rx + ry * ry + rz * rz);
        float start = (d_e + d_r) * fs_c;
        int i0 = (int)floorf(start);
        i0 = min(max(i0, 0), Tn - 2 - (Ln - 1) - 7);  // never fires in practice
        float frac = start - (float)i0;
        int i0a = i0 & ~3;
        my_d = i0 & 3;
        my_g = tid >> 4;
        packed = make_float2(frac, __int_as_float(tid * Tn + i0a));

        unsigned m = __match_any_sync(0xFFFFFFFFu, (my_g << 2) | my_d);
        unsigned lt = m & ((1u << (tid & 31)) - 1u);
        my_rank = __popc(lt);
        if (lt == 0u) s_cnt[my_g][my_d] = __popc(m);
    }
    __syncthreads();
    if (tid < 4) {
        int c0 = s_cnt[tid][0], c1 = s_cnt[tid][1], c2 = s_cnt[tid][2], c3 = s_cnt[tid][3];
        int o0 = 0, o1 = c0, o2 = c0 + c1, o3 = c0 + c1 + c2;
        s_start[tid][0] = o0; s_start[tid][1] = o1; s_start[tid][2] = o2; s_start[tid][3] = o3;
        s_bnd[tid][0] = o1; s_bnd[tid][1] = o2; s_bnd[tid][2] = o3; s_bnd[tid][3] = 16;
    }
    __syncthreads();
    if (tid < Rn) {
        s_sorted[my_g * 16 + s_start[my_g][my_d] + my_rank] = packed;
    }
    __syncthreads();

    const int g = tid >> 6;        // r-group 0..3
    const int t = tid & 63;        // l-thread: l = 4t..4t+3
    const int lane = tid & 31;

    const float* recb = rec + (size_t)b1 * Rn * Tn + 4 * t;

    u64 A01 = pack2(0.0f, 0.0f);
    u64 A23 = pack2(0.0f, 0.0f);
    u64 Q01 = pack2(0.0f, 0.0f);
    u64 Q23 = pack2(0.0f, 0.0f);

    const int base = g * 16;
    const int e0b = s_bnd[g][0];
    const int e1b = s_bnd[g][1];
    const int e2b = s_bnd[g][2];

    int k = 0;
    for (; k < e0b; ++k) body_d<0>(s_sorted[base + k], recb, lane, A01, A23, Q01, Q23);
    for (; k < e1b; ++k) body_d<1>(s_sorted[base + k], recb, lane, A01, A23, Q01, Q23);
    for (; k < e2b; ++k) body_d<2>(s_sorted[base + k], recb, lane, A01, A23, Q01, Q23);
    for (; k < 16;  ++k) body_d<3>(s_sorted[base + k], recb, lane, A01, A23, Q01, Q23);

    float a0, a1, a2, a3, q0, q1, q2, q3;
    unpack2(A01, a0, a1);
    unpack2(A23, a2, a3);
    unpack2(Q01, q0, q1);
    unpack2(Q23, q2, q3);

    // store per-group partials
    {
        float4* p1 = (float4*)&s_s1[g * Ln + 4 * t];
        float4* p2 = (float4*)&s_s2[g * Ln + 4 * t];
        *p1 = make_float4(a0, a1, a2, a3);
        *p2 = make_float4(q0, q1, q2, q3);
    }
    __syncthreads();

    // combine across the 4 r-groups: thread tid owns l = tid
    float S1 = s_s1[tid] + s_s1[Ln + tid] + s_s1[2 * Ln + tid] + s_s1[3 * Ln + tid];
    float S2 = s_s2[tid] + s_s2[Ln + tid] + s_s2[2 * Ln + tid] + s_s2[3 * Ln + tid];

    // Hann half-window at l = tid
    float wl = 0.5f - 0.5f * cosf(3.14159265358979323846f * (float)tid * (1.0f / 255.0f));
    float sw1 = wl * S1;
    float sw2 = (wl * wl) * S2;

    float num_p = sw2;
    float den_p = (sw2 - sw1 * sw1 * (1.0f / (float)Rn)) * (1.0f / (float)(Rn - 1));

    const unsigned FULL = 0xFFFFFFFFu;
#pragma unroll
    for (int off = 16; off > 0; off >>= 1) {
        num_p += __shfl_down_sync(FULL, num_p, off);
        den_p += __shfl_down_sync(FULL, den_p, off);
    }
    const int warp = tid >> 5;
    if (lane == 0) {
        s_red[warp * 2 + 0] = num_p;
        s_red[warp * 2 + 1] = den_p;
    }
    __syncthreads();
    if (warp == 0) {
        float n  = (lane < 8) ? s_red[lane * 2 + 0] : 0.0f;
        float dd = (lane < 8) ? s_red[lane * 2 + 1] : 0.0f;
#pragma unroll
        for (int off = 4; off > 0; off >>= 1) {
            n  += __shfl_down_sync(FULL, n, off);
            dd += __shfl_down_sync(FULL, dd, off);
        }
        if (lane == 0) {
            float num = n * (1.0f / ((float)Rn * (float)Ln));
            float den = dd * (1.0f / (float)Ln) + 0.001f;
            out[(size_t)b1 * B2n + b2] = num / den;
        }
    }
}

extern "C" void kernel_launch(void* const* d_in, const int* in_sizes, int n_in,
                              void* d_out, int out_size)
{
    const float* recordings         = (const float*)d_in[0];
    const float* sample_locations   = (const float*)d_in[1];
    const float* emitter_location   = (const float*)d_in[2];
    const float* receiver_locations = (const float*)d_in[3];
    float* out = (float*)d_out;

    dim3 grid(B2n, B1n);
    dim3 block(Ln);
    tof_predictor_kernel<<<grid, block>>>(recordings, sample_locations,
                                          emitter_location, receiver_locations, out);
}